// round 11
// baseline (speedup 1.0000x reference)
#include <cuda_runtime.h>
#include <cuda_bf16.h>
#include <cstdint>

#define KDIM   64
#define NPTS   32768
#define NCODES 8192
#define PTILE  128
#define CTILE  64
#define NT     (NCODES / CTILE)    // 128 code tiles
#define TPB    128                 // 4 warps x 32 rows = 128 points

// ---------------- device scratch (no allocations allowed) ----------------
__device__ __align__(16) __nv_bfloat16 g_lah[NPTS * KDIM];
__device__ __align__(16) __nv_bfloat16 g_lal[NPTS * KDIM];
__device__ __align__(16) __nv_bfloat16 g_cbh[NCODES * KDIM];
__device__ __align__(16) __nv_bfloat16 g_cbl[NCODES * KDIM];
__device__ float g_c2h[NCODES];            // 0.5*||c||^2 (fp32 exact)
__device__ int2  g_top2[NPTS];             // top-2 candidates per point

// ---------------- helpers ----------------
__device__ __forceinline__ uint32_t smem_u32(const void* p) {
    uint32_t a;
    asm("{ .reg .u64 t; cvta.to.shared.u64 t, %1; cvt.u32.u64 %0, t; }"
        : "=r"(a) : "l"(p));
    return a;
}
#define LDSM4(r, a)                                                          \
    asm volatile("ldmatrix.sync.aligned.m8n8.x4.shared.b16 {%0,%1,%2,%3}, [%4];" \
        : "=r"((r)[0]), "=r"((r)[1]), "=r"((r)[2]), "=r"((r)[3]) : "r"(a))

#define MMA(D, A, B0, B1)                                                    \
    asm volatile("mma.sync.aligned.m16n8k16.row.col.f32.bf16.bf16.f32 "      \
        "{%0,%1,%2,%3}, {%4,%5,%6,%7}, {%8,%9}, {%0,%1,%2,%3};"              \
        : "+f"((D)[0]), "+f"((D)[1]), "+f"((D)[2]), "+f"((D)[3])             \
        : "r"((A)[0]), "r"((A)[1]), "r"((A)[2]), "r"((A)[3]),                \
          "r"(B0), "r"(B1))

#define TOP2(V1, I1, V2, I2, s, idx) do {                                    \
    if ((s) > (V1)) { V2 = V1; I2 = I1; V1 = (s); I1 = (idx); }              \
    else if ((s) > (V2)) { V2 = (s); I2 = (idx); }                           \
} while (0)

__device__ __forceinline__ void merge2(float& v1, int& i1, float& v2, int& i2,
                                       float ov1, int oi1, float ov2, int oi2) {
    if (ov1 > v1) {
        if (v1 >= ov2) { v2 = v1; i2 = i1; } else { v2 = ov2; i2 = oi2; }
        v1 = ov1; i1 = oi1;
    } else if (ov1 > v2) { v2 = ov1; i2 = oi1; }
}

// ---------------- prekernels ----------------
__global__ void split_lat(const float* __restrict__ x) {
    int i = blockIdx.x * blockDim.x + threadIdx.x;
    float v = x[i];
    __nv_bfloat16 h = __float2bfloat16(v);
    g_lah[i] = h;
    g_lal[i] = __float2bfloat16(v - __bfloat162float(h));
}
__global__ void split_cb(const float* __restrict__ x) {
    int i = blockIdx.x * blockDim.x + threadIdx.x;
    float v = x[i];
    __nv_bfloat16 h = __float2bfloat16(v);
    g_cbh[i] = h;
    g_cbl[i] = __float2bfloat16(v - __bfloat162float(h));
}
__global__ void c2k(const float* __restrict__ cb) {
    int i = blockIdx.x * blockDim.x + threadIdx.x;
    const float* row = cb + (size_t)i * KDIM;
    float s = 0.f;
#pragma unroll
    for (int j = 0; j < KDIM; j++) s = fmaf(row[j], row[j], s);
    g_c2h[i] = 0.5f * s;
}

// ---------------- B-tile staging (swizzled, double-buffered) ----------------
__device__ __forceinline__ void stage_B(char* sB, float (*c2s)[CTILE],
                                        int tid, int t, int b) {
    const uint4* srch = reinterpret_cast<const uint4*>(g_cbh) + (size_t)t * 512;
    const uint4* srcl = reinterpret_cast<const uint4*>(g_cbl) + (size_t)t * 512;
#pragma unroll
    for (int i = 0; i < 4; i++) {                  // 512 chunks / 128 threads
        int id = tid + i * TPB;
        int r = id >> 3, c = id & 7;
        int off = b * 16384 + r * 128 + ((c ^ (r & 7)) * 16);
        *reinterpret_cast<uint4*>(sB + off)        = srch[id];
        *reinterpret_cast<uint4*>(sB + off + 8192) = srcl[id];
    }
    if (tid < CTILE) c2s[b][tid] = g_c2h[t * CTILE + tid];
}

// ---------------- main HMMA kernel: 4 warps x 32 rows ----------------
__global__ __launch_bounds__(TPB, 3)
void vq_mma() {
    __shared__ __align__(16) uint4 sBq[2048];      // 32 KB: A staging, then B x2
    __shared__ float c2s[2][CTILE];
    char* sB = reinterpret_cast<char*>(sBq);
    const uint32_t sb = smem_u32(sBq);

    const int tid = threadIdx.x, lane = tid & 31, w = tid >> 5;
    const int pbase = blockIdx.x * PTILE;

    // ---- stage A (both splits) swizzled: [split][128 rows][128 B] ----
    {
        const uint4* srch = reinterpret_cast<const uint4*>(g_lah) + (size_t)pbase * 8;
        const uint4* srcl = reinterpret_cast<const uint4*>(g_lal) + (size_t)pbase * 8;
#pragma unroll
        for (int i = 0; i < 8; i++) {              // 1024 chunks / 128 threads
            int id = tid + i * TPB;
            int r = id >> 3, c = id & 7;
            int off = r * 128 + ((c ^ (r & 7)) * 16);
            *reinterpret_cast<uint4*>(sB + off)         = srch[id];
            *reinterpret_cast<uint4*>(sB + 16384 + off) = srcl[id];
        }
    }
    __syncthreads();

    // ---- A fragments into registers: 2 m-tiles x 4 kc x 4 regs x 2 splits ----
    uint32_t Ah[2][4][4], Al[2][4][4];
    {
        int ch = lane >> 4;                        // 0/1 : low/high 16B of kchunk
#pragma unroll
        for (int mt = 0; mt < 2; mt++) {
            int r = w * 32 + mt * 16 + (lane & 15);
#pragma unroll
            for (int kc = 0; kc < 4; kc++) {
                int c = kc * 2 + ch;
                uint32_t addr = sb + r * 128 + ((c ^ (r & 7)) * 16);
                LDSM4(Ah[mt][kc], addr);
                LDSM4(Al[mt][kc], addr + 16384);
            }
        }
    }
    __syncthreads();                               // A smem now reusable for B

    // top-2 state for 4 row-groups: (mt0,lo) (mt0,hi) (mt1,lo) (mt1,hi)
    float v1[4] = {-3.0e38f, -3.0e38f, -3.0e38f, -3.0e38f};
    float v2[4] = {-3.0e38f, -3.0e38f, -3.0e38f, -3.0e38f};
    int   i1[4] = {0, 0, 0, 0}, i2[4] = {1, 1, 1, 1};

    stage_B(sB, c2s, tid, 0, 0);
    __syncthreads();

    for (int t = 0; t < NT; t++) {
        const int b = t & 1;
        if (t + 1 < NT) stage_B(sB, c2s, tid, t + 1, b ^ 1);
        const uint32_t bbase = sb + b * 16384;

#pragma unroll
        for (int n = 0; n < 8; n++) {
            uint32_t Bh[4][2], Bl[4][2];
            {
                int row = n * 8 + (lane & 7);
                int chq = (lane >> 3) & 3;
#pragma unroll
                for (int p = 0; p < 2; p++) {
                    int c = p * 4 + chq;
                    uint32_t addr = bbase + row * 128 + ((c ^ (row & 7)) * 16);
                    uint32_t tmp[4];
                    LDSM4(tmp, addr);
                    Bh[2*p][0] = tmp[0]; Bh[2*p][1] = tmp[1];
                    Bh[2*p+1][0] = tmp[2]; Bh[2*p+1][1] = tmp[3];
                    LDSM4(tmp, addr + 8192);
                    Bl[2*p][0] = tmp[0]; Bl[2*p][1] = tmp[1];
                    Bl[2*p+1][0] = tmp[2]; Bl[2*p+1][1] = tmp[3];
                }
            }
            // 3 independent accumulator chains per m-tile (depth 4 each)
            float Dhh[2][4], Dhl[2][4], Dlh[2][4];
#pragma unroll
            for (int mt = 0; mt < 2; mt++)
#pragma unroll
                for (int q = 0; q < 4; q++) {
                    Dhh[mt][q] = 0.f; Dhl[mt][q] = 0.f; Dlh[mt][q] = 0.f;
                }
#pragma unroll
            for (int kc = 0; kc < 4; kc++) {
#pragma unroll
                for (int mt = 0; mt < 2; mt++) {
                    MMA(Dhh[mt], Ah[mt][kc], Bh[kc][0], Bh[kc][1]);
                    MMA(Dhl[mt], Ah[mt][kc], Bl[kc][0], Bl[kc][1]);
                    MMA(Dlh[mt], Al[mt][kc], Bh[kc][0], Bh[kc][1]);
                }
            }
            // ---- epilogue: score = dot - 0.5||c||^2, top-2 update ----
            int c0 = n * 8 + 2 * (lane & 3);
            int g0 = t * CTILE + c0;
            float ch0 = c2s[b][c0], ch1 = c2s[b][c0 + 1];
#pragma unroll
            for (int mt = 0; mt < 2; mt++) {
                float s0 = ((Dhh[mt][0] + Dhl[mt][0]) + Dlh[mt][0]) - ch0;
                float s1 = ((Dhh[mt][1] + Dhl[mt][1]) + Dlh[mt][1]) - ch1;
                float s2 = ((Dhh[mt][2] + Dhl[mt][2]) + Dlh[mt][2]) - ch0;
                float s3 = ((Dhh[mt][3] + Dhl[mt][3]) + Dlh[mt][3]) - ch1;
                int glo = 2 * mt, ghi = 2 * mt + 1;
                TOP2(v1[glo], i1[glo], v2[glo], i2[glo], s0, g0);
                TOP2(v1[glo], i1[glo], v2[glo], i2[glo], s1, g0 + 1);
                TOP2(v1[ghi], i1[ghi], v2[ghi], i2[ghi], s2, g0);
                TOP2(v1[ghi], i1[ghi], v2[ghi], i2[ghi], s3, g0 + 1);
            }
        }
        __syncthreads();
    }

    // ---- merge top-2 across the 4 lanes sharing each row ----
#pragma unroll
    for (int g = 0; g < 4; g++) {
#pragma unroll
        for (int off = 1; off <= 2; off <<= 1) {
            float ov1 = __shfl_xor_sync(~0u, v1[g], off);
            int   oi1 = __shfl_xor_sync(~0u, i1[g], off);
            float ov2 = __shfl_xor_sync(~0u, v2[g], off);
            int   oi2 = __shfl_xor_sync(~0u, i2[g], off);
            merge2(v1[g], i1[g], v2[g], i2[g], ov1, oi1, ov2, oi2);
        }
    }
    if ((lane & 3) == 0) {
        int r0 = lane >> 2;                        // 0..7
        int base = pbase + w * 32 + r0;
        g_top2[base]      = make_int2(i1[0], i2[0]);   // mt0 rows r0
        g_top2[base + 8]  = make_int2(i1[1], i2[1]);   // mt0 rows r0+8
        g_top2[base + 16] = make_int2(i1[2], i2[2]);   // mt1 rows r0+16
        g_top2[base + 24] = make_int2(i1[3], i2[3]);   // mt1 rows r0+24
    }
}

// ---------------- exact fp32 rescore of the two candidates ----------------
__global__ void rescore_kernel(const float* __restrict__ lat,
                               const float* __restrict__ cb,
                               float* __restrict__ out) {
    int p = blockIdx.x * blockDim.x + threadIdx.x;
    int2 cand = g_top2[p];
    const float4* x = reinterpret_cast<const float4*>(lat + (size_t)p * KDIM);
    float4 xr[KDIM / 4];
#pragma unroll
    for (int q = 0; q < KDIM / 4; q++) xr[q] = x[q];

    float sc[2];
    int   id[2] = {cand.x, cand.y};
#pragma unroll
    for (int j = 0; j < 2; j++) {
        const float4* c = reinterpret_cast<const float4*>(cb + (size_t)id[j] * KDIM);
        float a0 = 0.f, a1 = 0.f, a2 = 0.f, a3 = 0.f;
#pragma unroll
        for (int q = 0; q < KDIM / 4; q++) {
            float4 cv = c[q];
            a0 = fmaf(xr[q].x, cv.x, a0);
            a1 = fmaf(xr[q].y, cv.y, a1);
            a2 = fmaf(xr[q].z, cv.z, a2);
            a3 = fmaf(xr[q].w, cv.w, a3);
        }
        sc[j] = ((a0 + a1) + (a2 + a3)) - g_c2h[id[j]];
    }
    int best = (sc[1] > sc[0] || (sc[1] == sc[0] && id[1] < id[0])) ? id[1] : id[0];
    out[p] = (float)best;
}

// ---------------- launch ----------------
extern "C" void kernel_launch(void* const* d_in, const int* in_sizes, int n_in,
                              void* d_out, int out_size) {
    const float* lat = (const float*)d_in[0];
    const float* cb  = (n_in > 1) ? (const float*)d_in[1] : (const float*)d_in[0];
    int cb_idx = -1, lat_idx = -1;
    for (int i = 0; i < n_in; i++) {
        if (in_sizes[i] == 524288)  cb_idx  = i;
        if (in_sizes[i] == 8388608) lat_idx = i;
    }
    if (cb_idx >= 0) {
        cb = (const float*)d_in[cb_idx];
        for (int i = 0; i < n_in; i++)
            if (i != cb_idx && (in_sizes[i] == 2097152 || in_sizes[i] == 8388608)) {
                lat = (const float*)d_in[i]; break;
            }
    } else if (lat_idx >= 0) {
        lat = (const float*)d_in[lat_idx];
        for (int i = 0; i < n_in; i++)
            if (i != lat_idx && in_sizes[i] == 2097152) { cb = (const float*)d_in[i]; break; }
    }
    float* out = (float*)d_out;

    split_lat<<<(NPTS * KDIM) / 256, 256>>>(lat);
    split_cb<<<(NCODES * KDIM) / 256, 256>>>(cb);
    c2k<<<NCODES / 256, 256>>>(cb);
    vq_mma<<<NPTS / PTILE, TPB>>>();
    rescore_kernel<<<NPTS / 128, 128>>>(lat, cb, out);
}

// round 12
// speedup vs baseline: 1.1910x; 1.1910x over previous
#include <cuda_runtime.h>
#include <cuda_bf16.h>
#include <cstdint>

#define KDIM   64
#define NPTS   32768
#define NCODES 8192
#define PTILE  128
#define CTILE  64
#define NTH    64                  // tiles per code-half (4096 / CTILE)
#define TPB    256                 // 8 warps x 16 rows = 128 points

// ---------------- device scratch (no allocations allowed) ----------------
__device__ __align__(16) __nv_bfloat16 g_lah[NPTS * KDIM];
__device__ __align__(16) __nv_bfloat16 g_lal[NPTS * KDIM];
__device__ __align__(16) __nv_bfloat16 g_cbh[NCODES * KDIM];
__device__ __align__(16) __nv_bfloat16 g_cbl[NCODES * KDIM];
__device__ float g_c2h[NCODES];            // 0.5*||c||^2 (fp32 exact)
__device__ int2  g_t2a[NPTS];              // top-2 in codes [0, 4096)
__device__ int2  g_t2b[NPTS];              // top-2 in codes [4096, 8192)

// ---------------- helpers ----------------
__device__ __forceinline__ uint32_t smem_u32(const void* p) {
    uint32_t a;
    asm("{ .reg .u64 t; cvta.to.shared.u64 t, %1; cvt.u32.u64 %0, t; }"
        : "=r"(a) : "l"(p));
    return a;
}
#define LDSM4(r, a)                                                          \
    asm volatile("ldmatrix.sync.aligned.m8n8.x4.shared.b16 {%0,%1,%2,%3}, [%4];" \
        : "=r"((r)[0]), "=r"((r)[1]), "=r"((r)[2]), "=r"((r)[3]) : "r"(a))

#define MMA(D, A, B0, B1)                                                    \
    asm volatile("mma.sync.aligned.m16n8k16.row.col.f32.bf16.bf16.f32 "      \
        "{%0,%1,%2,%3}, {%4,%5,%6,%7}, {%8,%9}, {%0,%1,%2,%3};"              \
        : "+f"((D)[0]), "+f"((D)[1]), "+f"((D)[2]), "+f"((D)[3])             \
        : "r"((A)[0]), "r"((A)[1]), "r"((A)[2]), "r"((A)[3]),                \
          "r"(B0), "r"(B1))

#define TOP2(V1, I1, V2, I2, s, idx) do {                                    \
    if ((s) > (V1)) { V2 = V1; I2 = I1; V1 = (s); I1 = (idx); }              \
    else if ((s) > (V2)) { V2 = (s); I2 = (idx); }                           \
} while (0)

__device__ __forceinline__ void merge2(float& v1, int& i1, float& v2, int& i2,
                                       float ov1, int oi1, float ov2, int oi2) {
    if (ov1 > v1) {
        if (v1 >= ov2) { v2 = v1; i2 = i1; } else { v2 = ov2; i2 = oi2; }
        v1 = ov1; i1 = oi1;
    } else if (ov1 > v2) { v2 = ov1; i2 = oi1; }
}

// ---------------- prekernels ----------------
__global__ void split_lat(const float* __restrict__ x) {
    int i = blockIdx.x * blockDim.x + threadIdx.x;
    float v = x[i];
    __nv_bfloat16 h = __float2bfloat16(v);
    g_lah[i] = h;
    g_lal[i] = __float2bfloat16(v - __bfloat162float(h));
}
__global__ void split_cb(const float* __restrict__ x) {
    int i = blockIdx.x * blockDim.x + threadIdx.x;
    float v = x[i];
    __nv_bfloat16 h = __float2bfloat16(v);
    g_cbh[i] = h;
    g_cbl[i] = __float2bfloat16(v - __bfloat162float(h));
}
__global__ void c2k(const float* __restrict__ cb) {
    int i = blockIdx.x * blockDim.x + threadIdx.x;
    const float* row = cb + (size_t)i * KDIM;
    float s = 0.f;
#pragma unroll
    for (int j = 0; j < KDIM; j++) s = fmaf(row[j], row[j], s);
    g_c2h[i] = 0.5f * s;
}

// ---------------- B-tile staging (swizzled, double-buffered) ----------------
__device__ __forceinline__ void stage_B(char* sB, float (*c2s)[CTILE],
                                        int tid, int gt, int b) {
    const uint4* srch = reinterpret_cast<const uint4*>(g_cbh) + (size_t)gt * 512;
    const uint4* srcl = reinterpret_cast<const uint4*>(g_cbl) + (size_t)gt * 512;
#pragma unroll
    for (int i = 0; i < 2; i++) {                  // 512 chunks / 256 threads
        int id = tid + i * TPB;
        int r = id >> 3, c = id & 7;
        int off = b * 16384 + r * 128 + ((c ^ (r & 7)) * 16);
        *reinterpret_cast<uint4*>(sB + off)        = srch[id];
        *reinterpret_cast<uint4*>(sB + off + 8192) = srcl[id];
    }
    if (tid < CTILE) c2s[b][tid] = g_c2h[gt * CTILE + tid];
}

// ---------------- main HMMA kernel: 512 CTAs (point-block x code-half) ------
__global__ __launch_bounds__(TPB, 3)
void vq_mma() {
    __shared__ __align__(16) uint4 sBq[2048];      // 32 KB: A staging, then B x2
    __shared__ float c2s[2][CTILE];
    char* sB = reinterpret_cast<char*>(sBq);
    const uint32_t sb = smem_u32(sBq);

    const int tid = threadIdx.x, lane = tid & 31, w = tid >> 5;
    const int pb   = blockIdx.x >> 1;              // point block 0..255
    const int half = blockIdx.x & 1;               // code half 0/1
    const int pbase = pb * PTILE;
    const int tbase = half * NTH;                  // first global tile

    // ---- stage A (both splits) swizzled: [split][128 rows][128 B] ----
    {
        const uint4* srch = reinterpret_cast<const uint4*>(g_lah) + (size_t)pbase * 8;
        const uint4* srcl = reinterpret_cast<const uint4*>(g_lal) + (size_t)pbase * 8;
#pragma unroll
        for (int i = 0; i < 4; i++) {              // 1024 chunks / 256 threads
            int id = tid + i * TPB;
            int r = id >> 3, c = id & 7;
            int off = r * 128 + ((c ^ (r & 7)) * 16);
            *reinterpret_cast<uint4*>(sB + off)         = srch[id];
            *reinterpret_cast<uint4*>(sB + 16384 + off) = srcl[id];
        }
    }
    __syncthreads();

    // ---- A fragments into registers (held for all 64 tiles) ----
    uint32_t Ah[4][4], Al[4][4];
    {
        int r = w * 16 + (lane & 15);
        int ch = lane >> 4;                        // 0/1 : low/high 16B of kchunk
#pragma unroll
        for (int kc = 0; kc < 4; kc++) {
            int c = kc * 2 + ch;
            uint32_t addr = sb + r * 128 + ((c ^ (r & 7)) * 16);
            LDSM4(Ah[kc], addr);
            LDSM4(Al[kc], addr + 16384);
        }
    }
    __syncthreads();                               // A smem now reusable for B

    float v1a = -3.0e38f, v2a = -3.0e38f, v1b = -3.0e38f, v2b = -3.0e38f;
    int   i1a = 0, i2a = 1, i1b = 0, i2b = 1;

    stage_B(sB, c2s, tid, tbase, 0);
    __syncthreads();

    for (int t = 0; t < NTH; t++) {
        const int b = t & 1;
        if (t + 1 < NTH) stage_B(sB, c2s, tid, tbase + t + 1, b ^ 1);
        const uint32_t bbase = sb + b * 16384;

#pragma unroll
        for (int n = 0; n < 8; n++) {
            uint32_t Bh[4][2], Bl[4][2];
            {
                int row = n * 8 + (lane & 7);
                int chq = (lane >> 3) & 3;
#pragma unroll
                for (int p = 0; p < 2; p++) {
                    int c = p * 4 + chq;
                    uint32_t addr = bbase + row * 128 + ((c ^ (row & 7)) * 16);
                    uint32_t tmp[4];
                    LDSM4(tmp, addr);
                    Bh[2*p][0] = tmp[0]; Bh[2*p][1] = tmp[1];
                    Bh[2*p+1][0] = tmp[2]; Bh[2*p+1][1] = tmp[3];
                    LDSM4(tmp, addr + 8192);
                    Bl[2*p][0] = tmp[0]; Bl[2*p][1] = tmp[1];
                    Bl[2*p+1][0] = tmp[2]; Bl[2*p+1][1] = tmp[3];
                }
            }
            // 3 independent accumulator chains (depth 4 each)
            float Dhh[4] = {0.f, 0.f, 0.f, 0.f};
            float Dhl[4] = {0.f, 0.f, 0.f, 0.f};
            float Dlh[4] = {0.f, 0.f, 0.f, 0.f};
#pragma unroll
            for (int kc = 0; kc < 4; kc++) {
                MMA(Dhh, Ah[kc], Bh[kc][0], Bh[kc][1]);
                MMA(Dhl, Ah[kc], Bl[kc][0], Bl[kc][1]);
                MMA(Dlh, Al[kc], Bh[kc][0], Bh[kc][1]);
            }
            // ---- epilogue: score = dot - 0.5||c||^2, top-2 update ----
            int c0 = n * 8 + 2 * (lane & 3);
            int g0 = tbase * CTILE + t * CTILE + c0;
            float ch0 = c2s[b][c0], ch1 = c2s[b][c0 + 1];
            float s0 = ((Dhh[0] + Dhl[0]) + Dlh[0]) - ch0;
            float s1 = ((Dhh[1] + Dhl[1]) + Dlh[1]) - ch1;
            float s2 = ((Dhh[2] + Dhl[2]) + Dlh[2]) - ch0;
            float s3 = ((Dhh[3] + Dhl[3]) + Dlh[3]) - ch1;
            TOP2(v1a, i1a, v2a, i2a, s0, g0);
            TOP2(v1a, i1a, v2a, i2a, s1, g0 + 1);
            TOP2(v1b, i1b, v2b, i2b, s2, g0);
            TOP2(v1b, i1b, v2b, i2b, s3, g0 + 1);
        }
        __syncthreads();
    }

    // ---- merge top-2 across the 4 lanes sharing each row ----
#pragma unroll
    for (int off = 1; off <= 2; off <<= 1) {
        float ov1 = __shfl_xor_sync(~0u, v1a, off);
        int   oi1 = __shfl_xor_sync(~0u, i1a, off);
        float ov2 = __shfl_xor_sync(~0u, v2a, off);
        int   oi2 = __shfl_xor_sync(~0u, i2a, off);
        merge2(v1a, i1a, v2a, i2a, ov1, oi1, ov2, oi2);
        ov1 = __shfl_xor_sync(~0u, v1b, off);
        oi1 = __shfl_xor_sync(~0u, i1b, off);
        ov2 = __shfl_xor_sync(~0u, v2b, off);
        oi2 = __shfl_xor_sync(~0u, i2b, off);
        merge2(v1b, i1b, v2b, i2b, ov1, oi1, ov2, oi2);
    }
    if ((lane & 3) == 0) {
        int r0 = lane >> 2;
        int2* dst = half ? g_t2b : g_t2a;
        dst[pbase + w * 16 + r0]     = make_int2(i1a, i2a);
        dst[pbase + w * 16 + r0 + 8] = make_int2(i1b, i2b);
    }
}

// ---------------- exact fp32 rescore of the four candidates ----------------
__global__ void rescore_kernel(const float* __restrict__ lat,
                               const float* __restrict__ cb,
                               float* __restrict__ out) {
    int p = blockIdx.x * blockDim.x + threadIdx.x;
    int2 ca = g_t2a[p], cbnd = g_t2b[p];
    int id[4] = {ca.x, ca.y, cbnd.x, cbnd.y};

    const float4* x = reinterpret_cast<const float4*>(lat + (size_t)p * KDIM);
    float4 xr[KDIM / 4];
#pragma unroll
    for (int q = 0; q < KDIM / 4; q++) xr[q] = x[q];

    float bv = -3.0e38f; int bi = 0x7fffffff;
#pragma unroll
    for (int j = 0; j < 4; j++) {
        const float4* c = reinterpret_cast<const float4*>(cb + (size_t)id[j] * KDIM);
        float a0 = 0.f, a1 = 0.f, a2 = 0.f, a3 = 0.f;
#pragma unroll
        for (int q = 0; q < KDIM / 4; q++) {
            float4 cv = c[q];
            a0 = fmaf(xr[q].x, cv.x, a0);
            a1 = fmaf(xr[q].y, cv.y, a1);
            a2 = fmaf(xr[q].z, cv.z, a2);
            a3 = fmaf(xr[q].w, cv.w, a3);
        }
        float s = ((a0 + a1) + (a2 + a3)) - g_c2h[id[j]];
        if (s > bv || (s == bv && id[j] < bi)) { bv = s; bi = id[j]; }
    }
    out[p] = (float)bi;
}

// ---------------- launch ----------------
extern "C" void kernel_launch(void* const* d_in, const int* in_sizes, int n_in,
                              void* d_out, int out_size) {
    const float* lat = (const float*)d_in[0];
    const float* cb  = (n_in > 1) ? (const float*)d_in[1] : (const float*)d_in[0];
    int cb_idx = -1, lat_idx = -1;
    for (int i = 0; i < n_in; i++) {
        if (in_sizes[i] == 524288)  cb_idx  = i;
        if (in_sizes[i] == 8388608) lat_idx = i;
    }
    if (cb_idx >= 0) {
        cb = (const float*)d_in[cb_idx];
        for (int i = 0; i < n_in; i++)
            if (i != cb_idx && (in_sizes[i] == 2097152 || in_sizes[i] == 8388608)) {
                lat = (const float*)d_in[i]; break;
            }
    } else if (lat_idx >= 0) {
        lat = (const float*)d_in[lat_idx];
        for (int i = 0; i < n_in; i++)
            if (i != lat_idx && in_sizes[i] == 2097152) { cb = (const float*)d_in[i]; break; }
    }
    float* out = (float*)d_out;

    split_lat<<<(NPTS * KDIM) / 256, 256>>>(lat);
    split_cb<<<(NCODES * KDIM) / 256, 256>>>(cb);
    c2k<<<NCODES / 256, 256>>>(cb);
    vq_mma<<<(NPTS / PTILE) * 2, TPB>>>();
    rescore_kernel<<<NPTS / 128, 128>>>(lat, cb, out);
}

// round 13
// speedup vs baseline: 1.3614x; 1.1431x over previous
#include <cuda_runtime.h>
#include <cuda_bf16.h>
#include <cstdint>

#define KDIM   64
#define NPTS   32768
#define NCODES 8192
#define PTILE  128
#define CTILE  64
#define NTH    32                  // tiles per code-quarter (2048 / CTILE)
#define TPB    256                 // 8 warps x 16 rows = 128 points

// ---------------- device scratch (no allocations allowed) ----------------
__device__ __align__(16) __nv_bfloat16 g_lah[NPTS * KDIM];
__device__ __align__(16) __nv_bfloat16 g_lal[NPTS * KDIM];
__device__ __align__(16) __nv_bfloat16 g_cbh[NCODES * KDIM];
__device__ __align__(16) __nv_bfloat16 g_cbl[NCODES * KDIM];
__device__ float g_c2h[NCODES];            // 0.5*||c||^2 (fp32 exact)
__device__ int2  g_t2[4 * NPTS];           // top-2 per (quarter, point)

// ---------------- helpers ----------------
__device__ __forceinline__ uint32_t smem_u32(const void* p) {
    uint32_t a;
    asm("{ .reg .u64 t; cvta.to.shared.u64 t, %1; cvt.u32.u64 %0, t; }"
        : "=r"(a) : "l"(p));
    return a;
}
#define LDSM4(r, a)                                                          \
    asm volatile("ldmatrix.sync.aligned.m8n8.x4.shared.b16 {%0,%1,%2,%3}, [%4];" \
        : "=r"((r)[0]), "=r"((r)[1]), "=r"((r)[2]), "=r"((r)[3]) : "r"(a))

#define MMA(D, A, B0, B1)                                                    \
    asm volatile("mma.sync.aligned.m16n8k16.row.col.f32.bf16.bf16.f32 "      \
        "{%0,%1,%2,%3}, {%4,%5,%6,%7}, {%8,%9}, {%0,%1,%2,%3};"              \
        : "+f"((D)[0]), "+f"((D)[1]), "+f"((D)[2]), "+f"((D)[3])             \
        : "r"((A)[0]), "r"((A)[1]), "r"((A)[2]), "r"((A)[3]),                \
          "r"(B0), "r"(B1))

// zero-start MMA: D = A*B + 0  (avoids explicit D init)
#define MMA_Z(D, A, B0, B1)                                                  \
    asm volatile("mma.sync.aligned.m16n8k16.row.col.f32.bf16.bf16.f32 "      \
        "{%0,%1,%2,%3}, {%4,%5,%6,%7}, {%8,%9}, {%10,%10,%10,%10};"          \
        : "=f"((D)[0]), "=f"((D)[1]), "=f"((D)[2]), "=f"((D)[3])             \
        : "r"((A)[0]), "r"((A)[1]), "r"((A)[2]), "r"((A)[3]),                \
          "r"(B0), "r"(B1), "f"(0.0f))

#define TOP2(V1, I1, V2, I2, s, idx) do {                                    \
    if ((s) > (V1)) { V2 = V1; I2 = I1; V1 = (s); I1 = (idx); }              \
    else if ((s) > (V2)) { V2 = (s); I2 = (idx); }                           \
} while (0)

__device__ __forceinline__ void merge2(float& v1, int& i1, float& v2, int& i2,
                                       float ov1, int oi1, float ov2, int oi2) {
    if (ov1 > v1) {
        if (v1 >= ov2) { v2 = v1; i2 = i1; } else { v2 = ov2; i2 = oi2; }
        v1 = ov1; i1 = oi1;
    } else if (ov1 > v2) { v2 = ov1; i2 = oi1; }
}

// ---------------- prekernels ----------------
__global__ void split_lat(const float* __restrict__ x) {
    int i = blockIdx.x * blockDim.x + threadIdx.x;
    float v = x[i];
    __nv_bfloat16 h = __float2bfloat16(v);
    g_lah[i] = h;
    g_lal[i] = __float2bfloat16(v - __bfloat162float(h));
}
__global__ void split_cb(const float* __restrict__ x) {
    int i = blockIdx.x * blockDim.x + threadIdx.x;
    float v = x[i];
    __nv_bfloat16 h = __float2bfloat16(v);
    g_cbh[i] = h;
    g_cbl[i] = __float2bfloat16(v - __bfloat162float(h));
}
__global__ void c2k(const float* __restrict__ cb) {
    int i = blockIdx.x * blockDim.x + threadIdx.x;
    const float* row = cb + (size_t)i * KDIM;
    float s = 0.f;
#pragma unroll
    for (int j = 0; j < KDIM; j++) s = fmaf(row[j], row[j], s);
    g_c2h[i] = 0.5f * s;
}

// ---------------- B-tile staging (swizzled, double-buffered) ----------------
__device__ __forceinline__ void stage_B(char* sB, float (*c2s)[CTILE],
                                        int tid, int gt, int b) {
    const uint4* srch = reinterpret_cast<const uint4*>(g_cbh) + (size_t)gt * 512;
    const uint4* srcl = reinterpret_cast<const uint4*>(g_cbl) + (size_t)gt * 512;
#pragma unroll
    for (int i = 0; i < 2; i++) {                  // 512 chunks / 256 threads
        int id = tid + i * TPB;
        int r = id >> 3, c = id & 7;
        int off = b * 16384 + r * 128 + ((c ^ (r & 7)) * 16);
        *reinterpret_cast<uint4*>(sB + off)        = srch[id];
        *reinterpret_cast<uint4*>(sB + off + 8192) = srcl[id];
    }
    if (tid < CTILE) c2s[b][tid] = g_c2h[gt * CTILE + tid];
}

// ---------------- main HMMA kernel: 1024 CTAs (point-block x code-quarter) --
__global__ __launch_bounds__(TPB, 3)
void vq_mma() {
    __shared__ __align__(16) uint4 sBq[2048];      // 32 KB: A staging, then B x2
    __shared__ float c2s[2][CTILE];
    char* sB = reinterpret_cast<char*>(sBq);
    const uint32_t sb = smem_u32(sBq);

    const int tid = threadIdx.x, lane = tid & 31, w = tid >> 5;
    const int pb      = blockIdx.x >> 2;           // point block 0..255
    const int quarter = blockIdx.x & 3;            // code quarter 0..3
    const int pbase = pb * PTILE;
    const int tbase = quarter * NTH;               // first global tile

    // ---- stage A (both splits) swizzled: [split][128 rows][128 B] ----
    {
        const uint4* srch = reinterpret_cast<const uint4*>(g_lah) + (size_t)pbase * 8;
        const uint4* srcl = reinterpret_cast<const uint4*>(g_lal) + (size_t)pbase * 8;
#pragma unroll
        for (int i = 0; i < 4; i++) {              // 1024 chunks / 256 threads
            int id = tid + i * TPB;
            int r = id >> 3, c = id & 7;
            int off = r * 128 + ((c ^ (r & 7)) * 16);
            *reinterpret_cast<uint4*>(sB + off)         = srch[id];
            *reinterpret_cast<uint4*>(sB + 16384 + off) = srcl[id];
        }
    }
    __syncthreads();

    // ---- A fragments into registers (held for all 32 tiles) ----
    uint32_t Ah[4][4], Al[4][4];
    {
        int r = w * 16 + (lane & 15);
        int ch = lane >> 4;                        // 0/1 : low/high 16B of kchunk
#pragma unroll
        for (int kc = 0; kc < 4; kc++) {
            int c = kc * 2 + ch;
            uint32_t addr = sb + r * 128 + ((c ^ (r & 7)) * 16);
            LDSM4(Ah[kc], addr);
            LDSM4(Al[kc], addr + 16384);
        }
    }
    __syncthreads();                               // A smem now reusable for B

    float v1a = -3.0e38f, v2a = -3.0e38f, v1b = -3.0e38f, v2b = -3.0e38f;
    int   i1a = 0, i2a = 1, i1b = 0, i2b = 1;

    // n-invariant pieces of the B ldmatrix addresses:
    // row = n*8 + (lane&7)  ->  row&7 == lane&7, so swizzle xor is constant.
    const int rlow = lane & 7;
    const int chq  = (lane >> 3) & 3;
    const uint32_t bo0 = rlow * 128 + (((chq)     ^ rlow) * 16);  // p=0: c=chq
    const uint32_t bo1 = rlow * 128 + (((4 + chq) ^ rlow) * 16);  // p=1: c=4+chq

    stage_B(sB, c2s, tid, tbase, 0);
    __syncthreads();

    for (int t = 0; t < NTH; t++) {
        const int b = t & 1;
        if (t + 1 < NTH) stage_B(sB, c2s, tid, tbase + t + 1, b ^ 1);
        const uint32_t bbase = sb + b * 16384;

#pragma unroll
        for (int n = 0; n < 8; n++) {
            uint32_t Bh[4][2], Bl[4][2];
            {
                uint32_t a0 = bbase + bo0 + n * 1024;
                uint32_t a1 = bbase + bo1 + n * 1024;
                uint32_t tmp[4];
                LDSM4(tmp, a0);
                Bh[0][0] = tmp[0]; Bh[0][1] = tmp[1];
                Bh[1][0] = tmp[2]; Bh[1][1] = tmp[3];
                LDSM4(tmp, a0 + 8192);
                Bl[0][0] = tmp[0]; Bl[0][1] = tmp[1];
                Bl[1][0] = tmp[2]; Bl[1][1] = tmp[3];
                LDSM4(tmp, a1);
                Bh[2][0] = tmp[0]; Bh[2][1] = tmp[1];
                Bh[3][0] = tmp[2]; Bh[3][1] = tmp[3];
                LDSM4(tmp, a1 + 8192);
                Bl[2][0] = tmp[0]; Bl[2][1] = tmp[1];
                Bl[3][0] = tmp[2]; Bl[3][1] = tmp[3];
            }
            // single accumulator chain: all 3 products into one D
            float D[4];
            MMA_Z(D, Ah[0], Bh[0][0], Bh[0][1]);
#pragma unroll
            for (int kc = 1; kc < 4; kc++) MMA(D, Ah[kc], Bh[kc][0], Bh[kc][1]);
#pragma unroll
            for (int kc = 0; kc < 4; kc++) MMA(D, Ah[kc], Bl[kc][0], Bl[kc][1]);
#pragma unroll
            for (int kc = 0; kc < 4; kc++) MMA(D, Al[kc], Bh[kc][0], Bh[kc][1]);

            // ---- epilogue: score = dot - 0.5||c||^2, filtered top-2 ----
            int c0 = n * 8 + 2 * (lane & 3);
            int g0 = (tbase + t) * CTILE + c0;
            float ch0 = c2s[b][c0], ch1 = c2s[b][c0 + 1];
            float s0 = D[0] - ch0, s1 = D[1] - ch1;
            float s2 = D[2] - ch0, s3 = D[3] - ch1;
            float ma = fmaxf(s0, s1), mb = fmaxf(s2, s3);
            if (__any_sync(~0u, ma > v2a)) {       // rare after warm-up
                TOP2(v1a, i1a, v2a, i2a, s0, g0);
                TOP2(v1a, i1a, v2a, i2a, s1, g0 + 1);
            }
            if (__any_sync(~0u, mb > v2b)) {
                TOP2(v1b, i1b, v2b, i2b, s2, g0);
                TOP2(v1b, i1b, v2b, i2b, s3, g0 + 1);
            }
        }
        __syncthreads();
    }

    // ---- merge top-2 across the 4 lanes sharing each row ----
#pragma unroll
    for (int off = 1; off <= 2; off <<= 1) {
        float ov1 = __shfl_xor_sync(~0u, v1a, off);
        int   oi1 = __shfl_xor_sync(~0u, i1a, off);
        float ov2 = __shfl_xor_sync(~0u, v2a, off);
        int   oi2 = __shfl_xor_sync(~0u, i2a, off);
        merge2(v1a, i1a, v2a, i2a, ov1, oi1, ov2, oi2);
        ov1 = __shfl_xor_sync(~0u, v1b, off);
        oi1 = __shfl_xor_sync(~0u, i1b, off);
        ov2 = __shfl_xor_sync(~0u, v2b, off);
        oi2 = __shfl_xor_sync(~0u, i2b, off);
        merge2(v1b, i1b, v2b, i2b, ov1, oi1, ov2, oi2);
    }
    if ((lane & 3) == 0) {
        int r0 = lane >> 2;
        int2* dst = g_t2 + quarter * NPTS + pbase + w * 16;
        dst[r0]     = make_int2(i1a, i2a);
        dst[r0 + 8] = make_int2(i1b, i2b);
    }
}

// ---------------- exact fp32 rescore of the eight candidates ----------------
__global__ void rescore_kernel(const float* __restrict__ lat,
                               const float* __restrict__ cb,
                               float* __restrict__ out) {
    int p = blockIdx.x * blockDim.x + threadIdx.x;
    int id[8];
#pragma unroll
    for (int q = 0; q < 4; q++) {
        int2 c = g_t2[q * NPTS + p];
        id[2 * q] = c.x; id[2 * q + 1] = c.y;
    }
    const float4* x = reinterpret_cast<const float4*>(lat + (size_t)p * KDIM);
    float4 xr[KDIM / 4];
#pragma unroll
    for (int q = 0; q < KDIM / 4; q++) xr[q] = x[q];

    float bv = -3.0e38f; int bi = 0x7fffffff;
#pragma unroll
    for (int j = 0; j < 8; j++) {
        const float4* c = reinterpret_cast<const float4*>(cb + (size_t)id[j] * KDIM);
        float a0 = 0.f, a1 = 0.f, a2 = 0.f, a3 = 0.f;
#pragma unroll
        for (int q = 0; q < KDIM / 4; q++) {
            float4 cv = c[q];
            a0 = fmaf(xr[q].x, cv.x, a0);
            a1 = fmaf(xr[q].y, cv.y, a1);
            a2 = fmaf(xr[q].z, cv.z, a2);
            a3 = fmaf(xr[q].w, cv.w, a3);
        }
        float s = ((a0 + a1) + (a2 + a3)) - g_c2h[id[j]];
        if (s > bv || (s == bv && id[j] < bi)) { bv = s; bi = id[j]; }
    }
    out[p] = (float)bi;
}

// ---------------- launch ----------------
extern "C" void kernel_launch(void* const* d_in, const int* in_sizes, int n_in,
                              void* d_out, int out_size) {
    const float* lat = (const float*)d_in[0];
    const float* cb  = (n_in > 1) ? (const float*)d_in[1] : (const float*)d_in[0];
    int cb_idx = -1, lat_idx = -1;
    for (int i = 0; i < n_in; i++) {
        if (in_sizes[i] == 524288)  cb_idx  = i;
        if (in_sizes[i] == 8388608) lat_idx = i;
    }
    if (cb_idx >= 0) {
        cb = (const float*)d_in[cb_idx];
        for (int i = 0; i < n_in; i++)
            if (i != cb_idx && (in_sizes[i] == 2097152 || in_sizes[i] == 8388608)) {
                lat = (const float*)d_in[i]; break;
            }
    } else if (lat_idx >= 0) {
        lat = (const float*)d_in[lat_idx];
        for (int i = 0; i < n_in; i++)
            if (i != lat_idx && in_sizes[i] == 2097152) { cb = (const float*)d_in[i]; break; }
    }
    float* out = (float*)d_out;

    split_lat<<<(NPTS * KDIM) / 256, 256>>>(lat);
    split_cb<<<(NCODES * KDIM) / 256, 256>>>(cb);
    c2k<<<NCODES / 256, 256>>>(cb);
    vq_mma<<<(NPTS / PTILE) * 4, TPB>>>();
    rescore_kernel<<<NPTS / 128, 128>>>(lat, cb, out);
}

// round 15
// speedup vs baseline: 1.4195x; 1.0427x over previous
#include <cuda_runtime.h>
#include <cuda_bf16.h>
#include <cstdint>

#define KDIM   64
#define NPTS   32768
#define NCODES 8192
#define PTILE  128
#define CTILE  64
#define NTH    32                  // tiles per code-quarter (2048 / CTILE)
#define TPB    256                 // 8 warps x 16 rows = 128 points

// ---------------- device scratch (no allocations allowed) ----------------
__device__ __align__(16) __nv_bfloat16 g_lah[NPTS * KDIM];
__device__ __align__(16) __nv_bfloat16 g_lal[NPTS * KDIM];
__device__ __align__(16) __nv_bfloat16 g_cbh[NCODES * KDIM];
__device__ __align__(16) __nv_bfloat16 g_cbl[NCODES * KDIM];
__device__ float g_c2h[NCODES];            // 0.5*||c||^2 (fp32 exact)
__device__ int2  g_t2[4 * NPTS];           // top-2 per (quarter, point)

// ---------------- helpers ----------------
__device__ __forceinline__ uint32_t smem_u32(const void* p) {
    uint32_t a;
    asm("{ .reg .u64 t; cvta.to.shared.u64 t, %1; cvt.u32.u64 %0, t; }"
        : "=r"(a) : "l"(p));
    return a;
}
#define LDSM4(r, a)                                                          \
    asm volatile("ldmatrix.sync.aligned.m8n8.x4.shared.b16 {%0,%1,%2,%3}, [%4];" \
        : "=r"((r)[0]), "=r"((r)[1]), "=r"((r)[2]), "=r"((r)[3]) : "r"(a))

#define MMA(D, A, B0, B1)                                                    \
    asm volatile("mma.sync.aligned.m16n8k16.row.col.f32.bf16.bf16.f32 "      \
        "{%0,%1,%2,%3}, {%4,%5,%6,%7}, {%8,%9}, {%0,%1,%2,%3};"              \
        : "+f"((D)[0]), "+f"((D)[1]), "+f"((D)[2]), "+f"((D)[3])             \
        : "r"((A)[0]), "r"((A)[1]), "r"((A)[2]), "r"((A)[3]),                \
          "r"(B0), "r"(B1))

#define MMA_Z(D, A, B0, B1)                                                  \
    asm volatile("mma.sync.aligned.m16n8k16.row.col.f32.bf16.bf16.f32 "      \
        "{%0,%1,%2,%3}, {%4,%5,%6,%7}, {%8,%9}, {%10,%10,%10,%10};"          \
        : "=f"((D)[0]), "=f"((D)[1]), "=f"((D)[2]), "=f"((D)[3])             \
        : "r"((A)[0]), "r"((A)[1]), "r"((A)[2]), "r"((A)[3]),                \
          "r"(B0), "r"(B1), "f"(0.0f))

#define CP16(dst, src)                                                       \
    asm volatile("cp.async.cg.shared.global [%0], [%1], 16;"                 \
                 :: "r"(dst), "l"(src))
#define CP_COMMIT() asm volatile("cp.async.commit_group;" ::: "memory")
#define CP_WAIT0()  asm volatile("cp.async.wait_group 0;" ::: "memory")

#define TOP2(V1, I1, V2, I2, s, idx) do {                                    \
    if ((s) > (V1)) { V2 = V1; I2 = I1; V1 = (s); I1 = (idx); }              \
    else if ((s) > (V2)) { V2 = (s); I2 = (idx); }                           \
} while (0)

__device__ __forceinline__ void merge2(float& v1, int& i1, float& v2, int& i2,
                                       float ov1, int oi1, float ov2, int oi2) {
    if (ov1 > v1) {
        if (v1 >= ov2) { v2 = v1; i2 = i1; } else { v2 = ov2; i2 = oi2; }
        v1 = ov1; i1 = oi1;
    } else if (ov1 > v2) { v2 = ov1; i2 = oi1; }
}

// ---------------- prekernels ----------------
__global__ void split_lat(const float* __restrict__ x) {
    int i = blockIdx.x * blockDim.x + threadIdx.x;
    float v = x[i];
    __nv_bfloat16 h = __float2bfloat16(v);
    g_lah[i] = h;
    g_lal[i] = __float2bfloat16(v - __bfloat162float(h));
}
__global__ void split_cb(const float* __restrict__ x) {
    int i = blockIdx.x * blockDim.x + threadIdx.x;
    float v = x[i];
    __nv_bfloat16 h = __float2bfloat16(v);
    g_cbh[i] = h;
    g_cbl[i] = __float2bfloat16(v - __bfloat162float(h));
}
__global__ void c2k(const float* __restrict__ cb) {
    int i = blockIdx.x * blockDim.x + threadIdx.x;
    const float* row = cb + (size_t)i * KDIM;
    float s = 0.f;
#pragma unroll
    for (int j = 0; j < KDIM; j++) s = fmaf(row[j], row[j], s);
    g_c2h[i] = 0.5f * s;
}

// ---------------- B-tile staging via cp.async (swizzled, double-buffered) ---
__device__ __forceinline__ void stage_B_async(uint32_t sbB, float (*c2s)[CTILE],
                                              int tid, int gt, int b) {
    const char* srch = reinterpret_cast<const char*>(g_cbh) + (size_t)gt * 8192;
    const char* srcl = reinterpret_cast<const char*>(g_cbl) + (size_t)gt * 8192;
#pragma unroll
    for (int i = 0; i < 2; i++) {                  // 512 chunks / 256 threads
        int id = tid + i * TPB;
        int r = id >> 3, c = id & 7;
        uint32_t off = b * 16384 + r * 128 + ((c ^ (r & 7)) * 16);
        CP16(sbB + off,        srch + id * 16);
        CP16(sbB + off + 8192, srcl + id * 16);
    }
    CP_COMMIT();
    if (tid < CTILE) c2s[b][tid] = g_c2h[gt * CTILE + tid];
}

// ---------------- main HMMA kernel: 1024 CTAs (point-block x code-quarter) --
__global__ __launch_bounds__(TPB, 3)
void vq_mma() {
    __shared__ __align__(16) uint4 sBq[2048];      // 32 KB: A staging, then B x2
    __shared__ float c2s[2][CTILE];
    char* sB = reinterpret_cast<char*>(sBq);
    const uint32_t sb = smem_u32(sBq);

    const int tid = threadIdx.x, lane = tid & 31, w = tid >> 5;
    const int pb      = blockIdx.x >> 2;           // point block 0..255
    const int quarter = blockIdx.x & 3;            // code quarter 0..3
    const int pbase = pb * PTILE;
    const int tbase = quarter * NTH;               // first global tile

    // ---- stage A (both splits) swizzled: [split][128 rows][128 B] ----
    {
        const uint4* srch = reinterpret_cast<const uint4*>(g_lah) + (size_t)pbase * 8;
        const uint4* srcl = reinterpret_cast<const uint4*>(g_lal) + (size_t)pbase * 8;
#pragma unroll
        for (int i = 0; i < 4; i++) {              // 1024 chunks / 256 threads
            int id = tid + i * TPB;
            int r = id >> 3, c = id & 7;
            int off = r * 128 + ((c ^ (r & 7)) * 16);
            *reinterpret_cast<uint4*>(sB + off)         = srch[id];
            *reinterpret_cast<uint4*>(sB + 16384 + off) = srcl[id];
        }
    }
    __syncthreads();

    // ---- A fragments into registers (held for all 32 tiles) ----
    uint32_t Ah[4][4], Al[4][4];
    {
        int r = w * 16 + (lane & 15);
        int ch = lane >> 4;                        // 0/1 : low/high 16B of kchunk
#pragma unroll
        for (int kc = 0; kc < 4; kc++) {
            int c = kc * 2 + ch;
            uint32_t addr = sb + r * 128 + ((c ^ (r & 7)) * 16);
            LDSM4(Ah[kc], addr);
            LDSM4(Al[kc], addr + 16384);
        }
    }
    __syncthreads();                               // A smem now reusable for B

    float v1a = -3.0e38f, v2a = -3.0e38f, v1b = -3.0e38f, v2b = -3.0e38f;
    int   i1a = 0, i2a = 1, i1b = 0, i2b = 1;

    // n-invariant pieces of the B ldmatrix addresses
    const int rlow = lane & 7;
    const int chq  = (lane >> 3) & 3;
    const uint32_t bo0 = rlow * 128 + (((chq)     ^ rlow) * 16);
    const uint32_t bo1 = rlow * 128 + (((4 + chq) ^ rlow) * 16);

    stage_B_async(sb, c2s, tid, tbase, 0);
    CP_WAIT0();
    __syncthreads();

    for (int t = 0; t < NTH; t++) {
        const int b = t & 1;
        if (t + 1 < NTH) stage_B_async(sb, c2s, tid, tbase + t + 1, b ^ 1);
        const uint32_t bbase = sb + b * 16384;

#pragma unroll
        for (int n = 0; n < 8; n++) {
            uint32_t Bh[4][2], Bl[4][2];
            {
                uint32_t a0 = bbase + bo0 + n * 1024;
                uint32_t a1 = bbase + bo1 + n * 1024;
                uint32_t tmp[4];
                LDSM4(tmp, a0);
                Bh[0][0] = tmp[0]; Bh[0][1] = tmp[1];
                Bh[1][0] = tmp[2]; Bh[1][1] = tmp[3];
                LDSM4(tmp, a0 + 8192);
                Bl[0][0] = tmp[0]; Bl[0][1] = tmp[1];
                Bl[1][0] = tmp[2]; Bl[1][1] = tmp[3];
                LDSM4(tmp, a1);
                Bh[2][0] = tmp[0]; Bh[2][1] = tmp[1];
                Bh[3][0] = tmp[2]; Bh[3][1] = tmp[3];
                LDSM4(tmp, a1 + 8192);
                Bl[2][0] = tmp[0]; Bl[2][1] = tmp[1];
                Bl[3][0] = tmp[2]; Bl[3][1] = tmp[3];
            }
            // two independent accumulator chains: D1 = hh+lh (depth 8), D2 = hl (depth 4)
            float D1[4], D2[4];
            MMA_Z(D1, Ah[0], Bh[0][0], Bh[0][1]);
            MMA_Z(D2, Ah[0], Bl[0][0], Bl[0][1]);
#pragma unroll
            for (int kc = 1; kc < 4; kc++) {
                MMA(D1, Ah[kc], Bh[kc][0], Bh[kc][1]);
                MMA(D2, Ah[kc], Bl[kc][0], Bl[kc][1]);
            }
#pragma unroll
            for (int kc = 0; kc < 4; kc++)
                MMA(D1, Al[kc], Bh[kc][0], Bh[kc][1]);

            // ---- epilogue: score = dot - 0.5||c||^2, filtered top-2 ----
            int c0 = n * 8 + 2 * (lane & 3);
            int g0 = (tbase + t) * CTILE + c0;
            float ch0 = c2s[b][c0], ch1 = c2s[b][c0 + 1];
            float s0 = (D1[0] + D2[0]) - ch0, s1 = (D1[1] + D2[1]) - ch1;
            float s2 = (D1[2] + D2[2]) - ch0, s3 = (D1[3] + D2[3]) - ch1;
            float ma = fmaxf(s0, s1), mb = fmaxf(s2, s3);
            if (__any_sync(~0u, ma > v2a)) {       // rare after warm-up
                TOP2(v1a, i1a, v2a, i2a, s0, g0);
                TOP2(v1a, i1a, v2a, i2a, s1, g0 + 1);
            }
            if (__any_sync(~0u, mb > v2b)) {
                TOP2(v1b, i1b, v2b, i2b, s2, g0);
                TOP2(v1b, i1b, v2b, i2b, s3, g0 + 1);
            }
        }
        if (t + 1 < NTH) CP_WAIT0();
        __syncthreads();
    }

    // ---- merge top-2 across the 4 lanes sharing each row ----
#pragma unroll
    for (int off = 1; off <= 2; off <<= 1) {
        float ov1 = __shfl_xor_sync(~0u, v1a, off);
        int   oi1 = __shfl_xor_sync(~0u, i1a, off);
        float ov2 = __shfl_xor_sync(~0u, v2a, off);
        int   oi2 = __shfl_xor_sync(~0u, i2a, off);
        merge2(v1a, i1a, v2a, i2a, ov1, oi1, ov2, oi2);
        ov1 = __shfl_xor_sync(~0u, v1b, off);
        oi1 = __shfl_xor_sync(~0u, i1b, off);
        ov2 = __shfl_xor_sync(~0u, v2b, off);
        oi2 = __shfl_xor_sync(~0u, i2b, off);
        merge2(v1b, i1b, v2b, i2b, ov1, oi1, ov2, oi2);
    }
    if ((lane & 3) == 0) {
        int r0 = lane >> 2;
        int2* dst = g_t2 + quarter * NPTS + pbase + w * 16;
        dst[r0]     = make_int2(i1a, i2a);
        dst[r0 + 8] = make_int2(i1b, i2b);
    }
}

// ---------------- exact fp32 rescore of the eight candidates ----------------
__global__ void rescore_kernel(const float* __restrict__ lat,
                               const float* __restrict__ cb,
                               float* __restrict__ out) {
    int p = blockIdx.x * blockDim.x + threadIdx.x;
    int id[8];
#pragma unroll
    for (int q = 0; q < 4; q++) {
        int2 c = g_t2[q * NPTS + p];
        id[2 * q] = c.x; id[2 * q + 1] = c.y;
    }
    const float4* x = reinterpret_cast<const float4*>(lat + (size_t)p * KDIM);
    float4 xr[KDIM / 4];
#pragma unroll
    for (int q = 0; q < KDIM / 4; q++) xr[q] = x[q];

    float bv = -3.0e38f; int bi = 0x7fffffff;
#pragma unroll
    for (int j = 0; j < 8; j++) {
        const float4* c = reinterpret_cast<const float4*>(cb + (size_t)id[j] * KDIM);
        float a0 = 0.f, a1 = 0.f, a2 = 0.f, a3 = 0.f;
#pragma unroll
        for (int q = 0; q < KDIM / 4; q++) {
            float4 cv = c[q];
            a0 = fmaf(xr[q].x, cv.x, a0);
            a1 = fmaf(xr[q].y, cv.y, a1);
            a2 = fmaf(xr[q].z, cv.z, a2);
            a3 = fmaf(xr[q].w, cv.w, a3);
        }
        float s = ((a0 + a1) + (a2 + a3)) - g_c2h[id[j]];
        if (s > bv || (s == bv && id[j] < bi)) { bv = s; bi = id[j]; }
    }
    out[p] = (float)bi;
}

// ---------------- launch ----------------
extern "C" void kernel_launch(void* const* d_in, const int* in_sizes, int n_in,
                              void* d_out, int out_size) {
    const float* lat = (const float*)d_in[0];
    const float* cb  = (n_in > 1) ? (const float*)d_in[1] : (const float*)d_in[0];
    int cb_idx = -1, lat_idx = -1;
    for (int i = 0; i < n_in; i++) {
        if (in_sizes[i] == 524288)  cb_idx  = i;
        if (in_sizes[i] == 8388608) lat_idx = i;
    }
    if (cb_idx >= 0) {
        cb = (const float*)d_in[cb_idx];
        for (int i = 0; i < n_in; i++)
            if (i != cb_idx && (in_sizes[i] == 2097152 || in_sizes[i] == 8388608)) {
                lat = (const float*)d_in[i]; break;
            }
    } else if (lat_idx >= 0) {
        lat = (const float*)d_in[lat_idx];
        for (int i = 0; i < n_in; i++)
            if (i != lat_idx && in_sizes[i] == 2097152) { cb = (const float*)d_in[i]; break; }
    }
    float* out = (float*)d_out;

    split_lat<<<(NPTS * KDIM) / 256, 256>>>(lat);
    split_cb<<<(NCODES * KDIM) / 256, 256>>>(cb);
    c2k<<<NCODES / 256, 256>>>(cb);
    vq_mma<<<(NPTS / PTILE) * 4, TPB>>>();
    rescore_kernel<<<NPTS / 128, 128>>>(lat, cb, out);
}

// round 16
// speedup vs baseline: 2.0679x; 1.4567x over previous
#include <cuda_runtime.h>
#include <cuda_fp16.h>
#include <cstdint>

#define KDIM   64
#define NPTS   32768
#define NCODES 8192
#define PTILE  128
#define CTILE  64
#define NTH    32                  // tiles per code-quarter (2048 / CTILE)
#define TPB    256                 // 8 warps x 16 rows = 128 points

// ---------------- device scratch (no allocations allowed) ----------------
__device__ __align__(16) __half g_laf[NPTS * KDIM];
__device__ __align__(16) __half g_cbf[NCODES * KDIM];
__device__ float g_c2h[NCODES];            // 0.5*||c||^2 (fp32 exact)
__device__ int4  g_t3[4 * NPTS];           // top-3 per (quarter, point)

// ---------------- helpers ----------------
__device__ __forceinline__ uint32_t smem_u32(const void* p) {
    uint32_t a;
    asm("{ .reg .u64 t; cvta.to.shared.u64 t, %1; cvt.u32.u64 %0, t; }"
        : "=r"(a) : "l"(p));
    return a;
}
#define LDSM4(r, a)                                                          \
    asm volatile("ldmatrix.sync.aligned.m8n8.x4.shared.b16 {%0,%1,%2,%3}, [%4];" \
        : "=r"((r)[0]), "=r"((r)[1]), "=r"((r)[2]), "=r"((r)[3]) : "r"(a))

#define MMAH(D, A, B0, B1)                                                   \
    asm volatile("mma.sync.aligned.m16n8k16.row.col.f32.f16.f16.f32 "        \
        "{%0,%1,%2,%3}, {%4,%5,%6,%7}, {%8,%9}, {%0,%1,%2,%3};"              \
        : "+f"((D)[0]), "+f"((D)[1]), "+f"((D)[2]), "+f"((D)[3])             \
        : "r"((A)[0]), "r"((A)[1]), "r"((A)[2]), "r"((A)[3]),                \
          "r"(B0), "r"(B1))

#define MMAH_Z(D, A, B0, B1)                                                 \
    asm volatile("mma.sync.aligned.m16n8k16.row.col.f32.f16.f16.f32 "        \
        "{%0,%1,%2,%3}, {%4,%5,%6,%7}, {%8,%9}, {%10,%10,%10,%10};"          \
        : "=f"((D)[0]), "=f"((D)[1]), "=f"((D)[2]), "=f"((D)[3])             \
        : "r"((A)[0]), "r"((A)[1]), "r"((A)[2]), "r"((A)[3]),                \
          "r"(B0), "r"(B1), "f"(0.0f))

#define CP16(dst, src)                                                       \
    asm volatile("cp.async.cg.shared.global [%0], [%1], 16;"                 \
                 :: "r"(dst), "l"(src))
#define CP_COMMIT() asm volatile("cp.async.commit_group;" ::: "memory")
#define CP_WAIT0()  asm volatile("cp.async.wait_group 0;" ::: "memory")

// insert s into a 3-deep max list (strict >, preserves first-occurrence ties)
#define TOP3(V1, I1, V2, I2, V3, I3, s, idx) do {                            \
    if ((s) > (V3)) {                                                        \
        if ((s) > (V1)) { V3 = V2; I3 = I2; V2 = V1; I2 = I1;                \
                          V1 = (s); I1 = (idx); }                            \
        else if ((s) > (V2)) { V3 = V2; I3 = I2; V2 = (s); I2 = (idx); }     \
        else { V3 = (s); I3 = (idx); }                                       \
    }                                                                        \
} while (0)

// ---------------- prekernels ----------------
__global__ void tohalf_lat(const float* __restrict__ x) {
    int i = blockIdx.x * blockDim.x + threadIdx.x;
    g_laf[i] = __float2half(x[i]);
}
__global__ void tohalf_cb(const float* __restrict__ x) {
    int i = blockIdx.x * blockDim.x + threadIdx.x;
    g_cbf[i] = __float2half(x[i]);
}
__global__ void c2k(const float* __restrict__ cb) {
    int i = blockIdx.x * blockDim.x + threadIdx.x;
    const float* row = cb + (size_t)i * KDIM;
    float s = 0.f;
#pragma unroll
    for (int j = 0; j < KDIM; j++) s = fmaf(row[j], row[j], s);
    g_c2h[i] = 0.5f * s;
}

// ---------------- B-tile staging via cp.async (swizzled, double-buffered) ---
__device__ __forceinline__ void stage_B_async(uint32_t sbB, float (*c2s)[CTILE],
                                              int tid, int gt, int b) {
    const char* src = reinterpret_cast<const char*>(g_cbf) + (size_t)gt * 8192;
    {                                              // 512 chunks / 256 threads
        int id = tid;
        int r = id >> 3, c = id & 7;
        CP16(sbB + b * 8192 + r * 128 + ((c ^ (r & 7)) * 16), src + id * 16);
        id = tid + TPB;
        r = id >> 3; c = id & 7;
        CP16(sbB + b * 8192 + r * 128 + ((c ^ (r & 7)) * 16), src + id * 16);
    }
    CP_COMMIT();
    if (tid < CTILE) c2s[b][tid] = g_c2h[gt * CTILE + tid];
}

// ---------------- main HMMA kernel: 1024 CTAs (point-block x code-quarter) --
__global__ __launch_bounds__(TPB, 3)
void vq_mma() {
    __shared__ __align__(16) uint4 sBq[1024];      // 16 KB: A staging, then B x2
    __shared__ float c2s[2][CTILE];
    char* sB = reinterpret_cast<char*>(sBq);
    const uint32_t sb = smem_u32(sBq);

    const int tid = threadIdx.x, lane = tid & 31, w = tid >> 5;
    const int pb      = blockIdx.x >> 2;           // point block 0..255
    const int quarter = blockIdx.x & 3;            // code quarter 0..3
    const int pbase = pb * PTILE;
    const int tbase = quarter * NTH;               // first global tile

    // ---- stage A swizzled: [128 rows][128 B] (fp16, 64 dims = 128 B/row) ----
    {
        const uint4* src = reinterpret_cast<const uint4*>(g_laf) + (size_t)pbase * 8;
#pragma unroll
        for (int i = 0; i < 4; i++) {              // 1024 chunks / 256 threads
            int id = tid + i * TPB;
            int r = id >> 3, c = id & 7;
            *reinterpret_cast<uint4*>(sB + r * 128 + ((c ^ (r & 7)) * 16)) = src[id];
        }
    }
    __syncthreads();

    // ---- A fragments into registers (held for all 32 tiles) ----
    uint32_t A[4][4];
    {
        int r = w * 16 + (lane & 15);
        int ch = lane >> 4;                        // 0/1 : low/high 16B of kchunk
#pragma unroll
        for (int kc = 0; kc < 4; kc++) {
            int c = kc * 2 + ch;
            LDSM4(A[kc], sb + r * 128 + ((c ^ (r & 7)) * 16));
        }
    }
    __syncthreads();                               // A smem now reusable for B

    // top-3 state for two row groups (rows r, r+8 of this warp's 16)
    float v1a = -3.0e38f, v2a = -3.0e38f, v3a = -3.0e38f;
    float v1b = -3.0e38f, v2b = -3.0e38f, v3b = -3.0e38f;
    int   i1a = 0, i2a = 1, i3a = 2, i1b = 0, i2b = 1, i3b = 2;

    // n-invariant pieces of the B ldmatrix addresses
    const int rlow = lane & 7;
    const int chq  = (lane >> 3) & 3;
    const uint32_t bo0 = rlow * 128 + (((chq)     ^ rlow) * 16);
    const uint32_t bo1 = rlow * 128 + (((4 + chq) ^ rlow) * 16);

    stage_B_async(sb, c2s, tid, tbase, 0);
    CP_WAIT0();
    __syncthreads();

    for (int t = 0; t < NTH; t++) {
        const int b = t & 1;
        if (t + 1 < NTH) stage_B_async(sb, c2s, tid, tbase + t + 1, b ^ 1);
        const uint32_t bbase = sb + b * 8192;

#pragma unroll
        for (int n = 0; n < 8; n++) {
            uint32_t B[4][2];
            {
                uint32_t tmp[4];
                LDSM4(tmp, bbase + bo0 + n * 1024);
                B[0][0] = tmp[0]; B[0][1] = tmp[1];
                B[1][0] = tmp[2]; B[1][1] = tmp[3];
                LDSM4(tmp, bbase + bo1 + n * 1024);
                B[2][0] = tmp[0]; B[2][1] = tmp[1];
                B[3][0] = tmp[2]; B[3][1] = tmp[3];
            }
            float D[4];
            MMAH_Z(D, A[0], B[0][0], B[0][1]);
#pragma unroll
            for (int kc = 1; kc < 4; kc++) MMAH(D, A[kc], B[kc][0], B[kc][1]);

            // ---- epilogue: score = dot - 0.5||c||^2, filtered top-3 ----
            int c0 = n * 8 + 2 * (lane & 3);
            int g0 = (tbase + t) * CTILE + c0;
            float ch0 = c2s[b][c0], ch1 = c2s[b][c0 + 1];
            float s0 = D[0] - ch0, s1 = D[1] - ch1;
            float s2 = D[2] - ch0, s3 = D[3] - ch1;
            float ma = fmaxf(s0, s1), mb = fmaxf(s2, s3);
            if (__any_sync(~0u, ma > v3a)) {       // rare after warm-up
                TOP3(v1a, i1a, v2a, i2a, v3a, i3a, s0, g0);
                TOP3(v1a, i1a, v2a, i2a, v3a, i3a, s1, g0 + 1);
            }
            if (__any_sync(~0u, mb > v3b)) {
                TOP3(v1b, i1b, v2b, i2b, v3b, i3b, s2, g0);
                TOP3(v1b, i1b, v2b, i2b, v3b, i3b, s3, g0 + 1);
            }
        }
        if (t + 1 < NTH) CP_WAIT0();
        __syncthreads();
    }

    // ---- merge top-3 across the 4 lanes sharing each row (disjoint codes) ---
#pragma unroll
    for (int off = 1; off <= 2; off <<= 1) {
        float w1 = __shfl_xor_sync(~0u, v1a, off), w2 = __shfl_xor_sync(~0u, v2a, off),
              w3 = __shfl_xor_sync(~0u, v3a, off);
        int   j1 = __shfl_xor_sync(~0u, i1a, off), j2 = __shfl_xor_sync(~0u, i2a, off),
              j3 = __shfl_xor_sync(~0u, i3a, off);
        TOP3(v1a, i1a, v2a, i2a, v3a, i3a, w1, j1);
        TOP3(v1a, i1a, v2a, i2a, v3a, i3a, w2, j2);
        TOP3(v1a, i1a, v2a, i2a, v3a, i3a, w3, j3);
        w1 = __shfl_xor_sync(~0u, v1b, off); w2 = __shfl_xor_sync(~0u, v2b, off);
        w3 = __shfl_xor_sync(~0u, v3b, off);
        j1 = __shfl_xor_sync(~0u, i1b, off); j2 = __shfl_xor_sync(~0u, i2b, off);
        j3 = __shfl_xor_sync(~0u, i3b, off);
        TOP3(v1b, i1b, v2b, i2b, v3b, i3b, w1, j1);
        TOP3(v1b, i1b, v2b, i2b, v3b, i3b, w2, j2);
        TOP3(v1b, i1b, v2b, i2b, v3b, i3b, w3, j3);
    }
    if ((lane & 3) == 0) {
        int r0 = lane >> 2;
        int4* dst = g_t3 + quarter * NPTS + pbase + w * 16;
        dst[r0]     = make_int4(i1a, i2a, i3a, 0);
        dst[r0 + 8] = make_int4(i1b, i2b, i3b, 0);
    }
}

// ---------------- exact fp32 rescore of the twelve candidates ----------------
__global__ void rescore_kernel(const float* __restrict__ lat,
                               const float* __restrict__ cb,
                               float* __restrict__ out) {
    int p = blockIdx.x * blockDim.x + threadIdx.x;
    int id[12];
#pragma unroll
    for (int q = 0; q < 4; q++) {
        int4 c = g_t3[q * NPTS + p];
        id[3 * q] = c.x; id[3 * q + 1] = c.y; id[3 * q + 2] = c.z;
    }
    const float4* x = reinterpret_cast<const float4*>(lat + (size_t)p * KDIM);
    float4 xr[KDIM / 4];
#pragma unroll
    for (int q = 0; q < KDIM / 4; q++) xr[q] = x[q];

    float bv = -3.0e38f; int bi = 0x7fffffff;
#pragma unroll
    for (int j = 0; j < 12; j++) {
        const float4* c = reinterpret_cast<const float4*>(cb + (size_t)id[j] * KDIM);
        float a0 = 0.f, a1 = 0.f, a2 = 0.f, a3 = 0.f;
#pragma unroll
        for (int q = 0; q < KDIM / 4; q++) {
            float4 cv = c[q];
            a0 = fmaf(xr[q].x, cv.x, a0);
            a1 = fmaf(xr[q].y, cv.y, a1);
            a2 = fmaf(xr[q].z, cv.z, a2);
            a3 = fmaf(xr[q].w, cv.w, a3);
        }
        float s = ((a0 + a1) + (a2 + a3)) - g_c2h[id[j]];
        if (s > bv || (s == bv && id[j] < bi)) { bv = s; bi = id[j]; }
    }
    out[p] = (float)bi;
}

// ---------------- launch ----------------
extern "C" void kernel_launch(void* const* d_in, const int* in_sizes, int n_in,
                              void* d_out, int out_size) {
    const float* lat = (const float*)d_in[0];
    const float* cb  = (n_in > 1) ? (const float*)d_in[1] : (const float*)d_in[0];
    int cb_idx = -1, lat_idx = -1;
    for (int i = 0; i < n_in; i++) {
        if (in_sizes[i] == 524288)  cb_idx  = i;
        if (in_sizes[i] == 8388608) lat_idx = i;
    }
    if (cb_idx >= 0) {
        cb = (const float*)d_in[cb_idx];
        for (int i = 0; i < n_in; i++)
            if (i != cb_idx && (in_sizes[i] == 2097152 || in_sizes[i] == 8388608)) {
                lat = (const float*)d_in[i]; break;
            }
    } else if (lat_idx >= 0) {
        lat = (const float*)d_in[lat_idx];
        for (int i = 0; i < n_in; i++)
            if (i != lat_idx && in_sizes[i] == 2097152) { cb = (const float*)d_in[i]; break; }
    }
    float* out = (float*)d_out;

    tohalf_lat<<<(NPTS * KDIM) / 256, 256>>>(lat);
    tohalf_cb<<<(NCODES * KDIM) / 256, 256>>>(cb);
    c2k<<<NCODES / 256, 256>>>(cb);
    vq_mma<<<(NPTS / PTILE) * 4, TPB>>>();
    rescore_kernel<<<NPTS / 128, 128>>>(lat, cb, out);
}